// round 1
// baseline (speedup 1.0000x reference)
#include <cuda_runtime.h>
#include <cuda_bf16.h>

#define NN 100000
#define EE 1600000
#define DD 128
#define GG 64

// ---------------- device scratch (no allocations allowed) ----------------
__device__ float g_xn[(size_t)NN * DD];   // scaled features (layer input, reused both layers)
__device__ float g_agg[(size_t)NN * DD];  // scatter-add accumulator (reused both layers)
__device__ int   g_deg_out[NN];
__device__ int   g_deg_in[NN];
__device__ float g_nsrc[NN];
__device__ float g_ndst[NN];
__device__ float g_pool[GG * DD];
__device__ float g_cnt[GG];

// ---------------- kernels ----------------

__global__ void k_degree(const int* __restrict__ src, const int* __restrict__ dst, int E) {
    int i = blockIdx.x * blockDim.x + threadIdx.x;
    int stride = gridDim.x * blockDim.x;
    for (; i < E; i += stride) {
        atomicAdd(&g_deg_out[src[i]], 1);
        atomicAdd(&g_deg_in[dst[i]], 1);
    }
}

__global__ void k_norm(int N) {
    int i = blockIdx.x * blockDim.x + threadIdx.x;
    if (i < N) {
        g_nsrc[i] = rsqrtf((float)max(g_deg_out[i], 1));
        g_ndst[i] = rsqrtf((float)max(g_deg_in[i], 1));
    }
}

// xn = in_feat * nsrc   (float4 per thread)
__global__ void k_scale(const float* __restrict__ x, int N) {
    int i = blockIdx.x * blockDim.x + threadIdx.x;  // over N*32 float4s
    if (i >= N * 32) return;
    int n = i >> 5;
    float s = g_nsrc[n];
    float4 v = ((const float4*)x)[i];
    v.x *= s; v.y *= s; v.z *= s; v.w *= s;
    ((float4*)g_xn)[i] = v;
}

// one warp per edge: agg[dst] += xn[src]   (vector f32 reduction, 16B per lane)
__global__ void k_spmm(const int* __restrict__ src, const int* __restrict__ dst, int E) {
    int gt = blockIdx.x * blockDim.x + threadIdx.x;
    int e = gt >> 5;
    if (e >= E) return;
    int lane = gt & 31;
    int s = src[e];
    int d = dst[e];
    float4 v = *(const float4*)(g_xn + (size_t)s * DD + lane * 4);
    float* p = g_agg + (size_t)d * DD + lane * 4;
    asm volatile("red.global.add.v4.f32 [%0], {%1,%2,%3,%4};"
                 :: "l"(p), "f"(v.x), "f"(v.y), "f"(v.z), "f"(v.w) : "memory");
}

// fused layer-1 dense stage: g_xn = relu((g_agg * ndst) @ W1 + b1) * nsrc
// BM=64 rows/block, full N=128 cols, full K=128. 256 threads; 4x8 outputs/thread.
__global__ void __launch_bounds__(256) k_gemm1(const float* __restrict__ W,
                                               const float* __restrict__ b, int N) {
    extern __shared__ float smem[];
    float* sA = smem;            // 64 x 128
    float* sW = smem + 64 * 128; // 128 x 128

    int t = threadIdx.x;
    int row0 = blockIdx.x * 64;

    // stage W (16 float4 each)
    const float4* Wv = (const float4*)W;
    float4* sWv = (float4*)sW;
#pragma unroll
    for (int i = 0; i < 16; i++) sWv[t + i * 256] = Wv[t + i * 256];

    // stage A rows, pre-scaled by ndst (8 float4 each)
    float4* sAv = (float4*)sA;
#pragma unroll
    for (int i = 0; i < 8; i++) {
        int f = t + i * 256;         // 0..2047
        int r = f >> 5;              // row in tile
        int c = f & 31;              // float4 col
        int row = row0 + r;
        float4 v = make_float4(0.f, 0.f, 0.f, 0.f);
        if (row < N) {
            v = *(const float4*)(g_agg + (size_t)row * DD + c * 4);
            float s = g_ndst[row];
            v.x *= s; v.y *= s; v.z *= s; v.w *= s;
        }
        sAv[f] = v;
    }
    __syncthreads();

    int tx = t & 15;          // 16 col groups
    int ty = t >> 4;          // 16 row groups
    int r = ty * 4;
    int c0 = tx * 4;          // cols c0..c0+3 and c0+64..c0+67 (bank-conflict-free)
    int c1 = 64 + tx * 4;

    float acc[4][8];
#pragma unroll
    for (int i = 0; i < 4; i++)
#pragma unroll
        for (int j = 0; j < 8; j++) acc[i][j] = 0.f;

#pragma unroll 4
    for (int k = 0; k < 128; k++) {
        float a0 = sA[(r + 0) * 128 + k];
        float a1 = sA[(r + 1) * 128 + k];
        float a2 = sA[(r + 2) * 128 + k];
        float a3 = sA[(r + 3) * 128 + k];
        float4 w0 = *(float4*)&sW[k * 128 + c0];
        float4 w1 = *(float4*)&sW[k * 128 + c1];
        acc[0][0] += a0 * w0.x; acc[0][1] += a0 * w0.y; acc[0][2] += a0 * w0.z; acc[0][3] += a0 * w0.w;
        acc[0][4] += a0 * w1.x; acc[0][5] += a0 * w1.y; acc[0][6] += a0 * w1.z; acc[0][7] += a0 * w1.w;
        acc[1][0] += a1 * w0.x; acc[1][1] += a1 * w0.y; acc[1][2] += a1 * w0.z; acc[1][3] += a1 * w0.w;
        acc[1][4] += a1 * w1.x; acc[1][5] += a1 * w1.y; acc[1][6] += a1 * w1.z; acc[1][7] += a1 * w1.w;
        acc[2][0] += a2 * w0.x; acc[2][1] += a2 * w0.y; acc[2][2] += a2 * w0.z; acc[2][3] += a2 * w0.w;
        acc[2][4] += a2 * w1.x; acc[2][5] += a2 * w1.y; acc[2][6] += a2 * w1.z; acc[2][7] += a2 * w1.w;
        acc[3][0] += a3 * w0.x; acc[3][1] += a3 * w0.y; acc[3][2] += a3 * w0.z; acc[3][3] += a3 * w0.w;
        acc[3][4] += a3 * w1.x; acc[3][5] += a3 * w1.y; acc[3][6] += a3 * w1.z; acc[3][7] += a3 * w1.w;
    }

    float4 bv0 = *(const float4*)&b[c0];
    float4 bv1 = *(const float4*)&b[c1];
#pragma unroll
    for (int i = 0; i < 4; i++) {
        int row = row0 + r + i;
        if (row < N) {
            float s = g_nsrc[row];
            float4 o0, o1;
            o0.x = fmaxf(acc[i][0] + bv0.x, 0.f) * s;
            o0.y = fmaxf(acc[i][1] + bv0.y, 0.f) * s;
            o0.z = fmaxf(acc[i][2] + bv0.z, 0.f) * s;
            o0.w = fmaxf(acc[i][3] + bv0.w, 0.f) * s;
            o1.x = fmaxf(acc[i][4] + bv1.x, 0.f) * s;
            o1.y = fmaxf(acc[i][5] + bv1.y, 0.f) * s;
            o1.z = fmaxf(acc[i][6] + bv1.z, 0.f) * s;
            o1.w = fmaxf(acc[i][7] + bv1.w, 0.f) * s;
            *(float4*)(g_xn + (size_t)row * DD + c0) = o0;
            *(float4*)(g_xn + (size_t)row * DD + c1) = o1;
        }
    }
}

// per-graph sum of (agg2 * ndst) with smem privatization, + counts
__global__ void __launch_bounds__(256) k_pool(const int* __restrict__ gid, int N) {
    __shared__ float acc[GG * DD];  // 32 KB
    __shared__ float cnt[GG];
    int t = threadIdx.x;
    for (int i = t; i < GG * DD; i += 256) acc[i] = 0.f;
    if (t < GG) cnt[t] = 0.f;
    __syncthreads();

    int chunk = (N + gridDim.x - 1) / gridDim.x;
    int base = blockIdx.x * chunk;
    int end = min(base + chunk, N);
    int warp = t >> 5, lane = t & 31;
    for (int n = base + warp; n < end; n += 8) {
        int g = gid[n];
        float s = g_ndst[n];
        float4 v = *(const float4*)(g_agg + (size_t)n * DD + lane * 4);
        float* p = &acc[g * DD + lane * 4];
        atomicAdd(p + 0, v.x * s);
        atomicAdd(p + 1, v.y * s);
        atomicAdd(p + 2, v.z * s);
        atomicAdd(p + 3, v.w * s);
        if (lane == 0) atomicAdd(&cnt[g], 1.f);
    }
    __syncthreads();
    for (int i = t; i < GG * DD; i += 256) atomicAdd(&g_pool[i], acc[i]);
    if (t < GG) atomicAdd(&g_cnt[t], cnt[t]);
}

// out = (pool/cnt) @ W2 + b2    (tiny 64x128x128 GEMM)
__global__ void k_final(const float* __restrict__ W2, const float* __restrict__ b2,
                        float* __restrict__ out) {
    __shared__ float srow[DD];
    int g = blockIdx.x, t = threadIdx.x;
    srow[t] = g_pool[g * DD + t] / fmaxf(g_cnt[g], 1.f);
    __syncthreads();
    float a = b2[t];
#pragma unroll 8
    for (int k = 0; k < DD; k++) a += srow[k] * W2[k * DD + t];
    out[g * DD + t] = a;
}

// ---------------- launch ----------------
extern "C" void kernel_launch(void* const* d_in, const int* in_sizes, int n_in,
                              void* d_out, int out_size) {
    const float* in_feat = (const float*)d_in[0];
    const float* W1 = (const float*)d_in[1];
    const float* b1 = (const float*)d_in[2];
    const float* W2 = (const float*)d_in[3];
    const float* b2 = (const float*)d_in[4];
    const int* src = (const int*)d_in[5];
    const int* dst = (const int*)d_in[6];
    const int* gid = (const int*)d_in[7];
    int N = in_sizes[0] / DD;
    int E = in_sizes[5];
    (void)n_in; (void)out_size;

    void *p_agg, *p_do, *p_di, *p_pool, *p_cnt;
    cudaGetSymbolAddress(&p_agg, g_agg);
    cudaGetSymbolAddress(&p_do, g_deg_out);
    cudaGetSymbolAddress(&p_di, g_deg_in);
    cudaGetSymbolAddress(&p_pool, g_pool);
    cudaGetSymbolAddress(&p_cnt, g_cnt);

    static int smem_set = 0;
    if (!smem_set) {
        cudaFuncSetAttribute(k_gemm1, cudaFuncAttributeMaxDynamicSharedMemorySize,
                             (64 * 128 + 128 * 128) * (int)sizeof(float));
        smem_set = 1;
    }

    cudaMemsetAsync(p_do, 0, N * sizeof(int));
    cudaMemsetAsync(p_di, 0, N * sizeof(int));
    cudaMemsetAsync(p_agg, 0, (size_t)N * DD * sizeof(float));
    cudaMemsetAsync(p_pool, 0, GG * DD * sizeof(float));
    cudaMemsetAsync(p_cnt, 0, GG * sizeof(float));

    k_degree<<<1024, 256>>>(src, dst, E);
    k_norm<<<(N + 255) / 256, 256>>>(N);
    k_scale<<<(N * 32 + 255) / 256, 256>>>(in_feat, N);

    // layer 1 aggregate
    k_spmm<<<(E * 8 + 63) / 64, 256>>>(src, dst, E);  // grid = E/8 blocks of 8 warps
    // dense stage 1 (fused ndst / W1 / b1 / relu / nsrc)
    k_gemm1<<<(N + 63) / 64, 256, (64 * 128 + 128 * 128) * sizeof(float)>>>(W1, b1, N);

    // layer 2 aggregate
    cudaMemsetAsync(p_agg, 0, (size_t)N * DD * sizeof(float));
    k_spmm<<<(E * 8 + 63) / 64, 256>>>(src, dst, E);

    // pooling of agg2*ndst, then tiny GEMM with W2/b2
    k_pool<<<200, 256>>>(gid, N);
    k_final<<<GG, DD>>>(W2, b2, (float*)d_out);
}

// round 2
// speedup vs baseline: 1.8860x; 1.8860x over previous
#include <cuda_runtime.h>
#include <cuda_bf16.h>

#define NN 100000
#define EE 1600000
#define DD 128
#define GG 64

// ---------------- device scratch ----------------
__device__ float g_xn[(size_t)NN * DD];   // layer-2 input: relu(h1)*nsrc
__device__ float g_agg[(size_t)NN * DD];  // aggregation output (both layers)
__device__ int   g_deg_out[NN];
__device__ int   g_deg_in[NN];
__device__ float g_nsrc[NN];
__device__ float g_ndst[NN];
__device__ float g_pool[GG * DD];
__device__ float g_cnt[GG];
// CSR-by-dst build
__device__ int   g_off[NN + 1];
__device__ int   g_cursor[NN];
__device__ int   g_sorted[EE];
__device__ int   g_bsum[128];

// ---------------- degree / norm ----------------
__global__ void k_degree(const int* __restrict__ src, const int* __restrict__ dst, int E) {
    int i = blockIdx.x * blockDim.x + threadIdx.x;
    int stride = gridDim.x * blockDim.x;
    for (; i < E; i += stride) {
        atomicAdd(&g_deg_out[src[i]], 1);
        atomicAdd(&g_deg_in[dst[i]], 1);
    }
}

__global__ void k_norm(int N) {
    int i = blockIdx.x * blockDim.x + threadIdx.x;
    if (i < N) {
        g_nsrc[i] = rsqrtf((float)max(g_deg_out[i], 1));
        g_ndst[i] = rsqrtf((float)max(g_deg_in[i], 1));
    }
}

// ---------------- exclusive scan of deg_in -> g_off (chunk=1024/block) ----------------
__global__ void k_scan1(int N) {
    __shared__ int s[256];
    int t = threadIdx.x;
    int base = blockIdx.x * 1024 + t * 4;
    int v0 = 0, v1 = 0, v2 = 0, v3 = 0;
    if (base + 0 < N) v0 = g_deg_in[base + 0];
    if (base + 1 < N) v1 = g_deg_in[base + 1];
    if (base + 2 < N) v2 = g_deg_in[base + 2];
    if (base + 3 < N) v3 = g_deg_in[base + 3];
    int tsum = v0 + v1 + v2 + v3;
    s[t] = tsum;
    __syncthreads();
    for (int o = 1; o < 256; o <<= 1) {
        int x = (t >= o) ? s[t - o] : 0;
        __syncthreads();
        s[t] += x;
        __syncthreads();
    }
    int incl = s[t];
    int excl = incl - tsum;
    if (base + 0 < N) g_off[base + 0] = excl;
    if (base + 1 < N) g_off[base + 1] = excl + v0;
    if (base + 2 < N) g_off[base + 2] = excl + v0 + v1;
    if (base + 3 < N) g_off[base + 3] = excl + v0 + v1 + v2;
    if (t == 255) g_bsum[blockIdx.x] = incl;
}

__global__ void k_scan2(int B) {
    __shared__ int s[128];
    int t = threadIdx.x;
    int v = (t < B) ? g_bsum[t] : 0;
    s[t] = v;
    __syncthreads();
    for (int o = 1; o < 128; o <<= 1) {
        int x = (t >= o) ? s[t - o] : 0;
        __syncthreads();
        s[t] += x;
        __syncthreads();
    }
    if (t < B) g_bsum[t] = s[t] - v;  // exclusive
}

__global__ void k_scan3(int N, int E) {
    int i = blockIdx.x * blockDim.x + threadIdx.x;
    if (i < N) {
        int o = g_off[i] + g_bsum[i >> 10];
        g_off[i] = o;
        g_cursor[i] = o;
    }
    if (i == 0) g_off[N] = E;
}

// scatter edges into dst-sorted order
__global__ void k_scatter(const int* __restrict__ src, const int* __restrict__ dst, int E) {
    int i = blockIdx.x * blockDim.x + threadIdx.x;
    if (i < E) {
        int d = dst[i];
        int p = atomicAdd(&g_cursor[d], 1);
        g_sorted[p] = src[i];
    }
}

// ---------------- segmented SpMM: one warp per dst node, no atomics ----------------
template <bool SCALE_SRC>
__global__ void __launch_bounds__(256) k_spmm_seg(const float* __restrict__ feat,
                                                  float* __restrict__ out, int N) {
    int warp = (blockIdx.x * blockDim.x + threadIdx.x) >> 5;
    if (warp >= N) return;
    int c = (threadIdx.x & 31) * 4;
    int e = g_off[warp];
    int e1 = g_off[warp + 1];
    float4 acc = make_float4(0.f, 0.f, 0.f, 0.f);
    for (; e + 4 <= e1; e += 4) {
        int s0 = g_sorted[e + 0];
        int s1 = g_sorted[e + 1];
        int s2 = g_sorted[e + 2];
        int s3 = g_sorted[e + 3];
        float4 v0 = *(const float4*)(feat + (size_t)s0 * DD + c);
        float4 v1 = *(const float4*)(feat + (size_t)s1 * DD + c);
        float4 v2 = *(const float4*)(feat + (size_t)s2 * DD + c);
        float4 v3 = *(const float4*)(feat + (size_t)s3 * DD + c);
        float f0 = 1.f, f1 = 1.f, f2 = 1.f, f3 = 1.f;
        if (SCALE_SRC) { f0 = g_nsrc[s0]; f1 = g_nsrc[s1]; f2 = g_nsrc[s2]; f3 = g_nsrc[s3]; }
        acc.x += v0.x * f0 + v1.x * f1 + v2.x * f2 + v3.x * f3;
        acc.y += v0.y * f0 + v1.y * f1 + v2.y * f2 + v3.y * f3;
        acc.z += v0.z * f0 + v1.z * f1 + v2.z * f2 + v3.z * f3;
        acc.w += v0.w * f0 + v1.w * f1 + v2.w * f2 + v3.w * f3;
    }
    for (; e < e1; e++) {
        int s = g_sorted[e];
        float4 v = *(const float4*)(feat + (size_t)s * DD + c);
        float f = SCALE_SRC ? g_nsrc[s] : 1.f;
        acc.x += v.x * f; acc.y += v.y * f; acc.z += v.z * f; acc.w += v.w * f;
    }
    *(float4*)(out + (size_t)warp * DD + c) = acc;
}

// ---------------- fused dense stage 1: g_xn = relu((g_agg*ndst)@W1+b1)*nsrc ----------------
__global__ void __launch_bounds__(256) k_gemm1(const float* __restrict__ W,
                                               const float* __restrict__ b, int N) {
    extern __shared__ float smem[];
    float* sA = smem;            // 64 x 128
    float* sW = smem + 64 * 128; // 128 x 128

    int t = threadIdx.x;
    int row0 = blockIdx.x * 64;

    const float4* Wv = (const float4*)W;
    float4* sWv = (float4*)sW;
#pragma unroll
    for (int i = 0; i < 16; i++) sWv[t + i * 256] = Wv[t + i * 256];

    float4* sAv = (float4*)sA;
#pragma unroll
    for (int i = 0; i < 8; i++) {
        int f = t + i * 256;
        int r = f >> 5;
        int cc = f & 31;
        int row = row0 + r;
        float4 v = make_float4(0.f, 0.f, 0.f, 0.f);
        if (row < N) {
            v = *(const float4*)(g_agg + (size_t)row * DD + cc * 4);
            float s = g_ndst[row];
            v.x *= s; v.y *= s; v.z *= s; v.w *= s;
        }
        sAv[f] = v;
    }
    __syncthreads();

    int tx = t & 15;
    int ty = t >> 4;
    int r = ty * 4;
    int c0 = tx * 4;
    int c1 = 64 + tx * 4;

    float acc[4][8];
#pragma unroll
    for (int i = 0; i < 4; i++)
#pragma unroll
        for (int j = 0; j < 8; j++) acc[i][j] = 0.f;

#pragma unroll 4
    for (int k = 0; k < 128; k++) {
        float a0 = sA[(r + 0) * 128 + k];
        float a1 = sA[(r + 1) * 128 + k];
        float a2 = sA[(r + 2) * 128 + k];
        float a3 = sA[(r + 3) * 128 + k];
        float4 w0 = *(float4*)&sW[k * 128 + c0];
        float4 w1 = *(float4*)&sW[k * 128 + c1];
        acc[0][0] += a0 * w0.x; acc[0][1] += a0 * w0.y; acc[0][2] += a0 * w0.z; acc[0][3] += a0 * w0.w;
        acc[0][4] += a0 * w1.x; acc[0][5] += a0 * w1.y; acc[0][6] += a0 * w1.z; acc[0][7] += a0 * w1.w;
        acc[1][0] += a1 * w0.x; acc[1][1] += a1 * w0.y; acc[1][2] += a1 * w0.z; acc[1][3] += a1 * w0.w;
        acc[1][4] += a1 * w1.x; acc[1][5] += a1 * w1.y; acc[1][6] += a1 * w1.z; acc[1][7] += a1 * w1.w;
        acc[2][0] += a2 * w0.x; acc[2][1] += a2 * w0.y; acc[2][2] += a2 * w0.z; acc[2][3] += a2 * w0.w;
        acc[2][4] += a2 * w1.x; acc[2][5] += a2 * w1.y; acc[2][6] += a2 * w1.z; acc[2][7] += a2 * w1.w;
        acc[3][0] += a3 * w0.x; acc[3][1] += a3 * w0.y; acc[3][2] += a3 * w0.z; acc[3][3] += a3 * w0.w;
        acc[3][4] += a3 * w1.x; acc[3][5] += a3 * w1.y; acc[3][6] += a3 * w1.z; acc[3][7] += a3 * w1.w;
    }

    float4 bv0 = *(const float4*)&b[c0];
    float4 bv1 = *(const float4*)&b[c1];
#pragma unroll
    for (int i = 0; i < 4; i++) {
        int row = row0 + r + i;
        if (row < N) {
            float s = g_nsrc[row];
            float4 o0, o1;
            o0.x = fmaxf(acc[i][0] + bv0.x, 0.f) * s;
            o0.y = fmaxf(acc[i][1] + bv0.y, 0.f) * s;
            o0.z = fmaxf(acc[i][2] + bv0.z, 0.f) * s;
            o0.w = fmaxf(acc[i][3] + bv0.w, 0.f) * s;
            o1.x = fmaxf(acc[i][4] + bv1.x, 0.f) * s;
            o1.y = fmaxf(acc[i][5] + bv1.y, 0.f) * s;
            o1.z = fmaxf(acc[i][6] + bv1.z, 0.f) * s;
            o1.w = fmaxf(acc[i][7] + bv1.w, 0.f) * s;
            *(float4*)(g_xn + (size_t)row * DD + c0) = o0;
            *(float4*)(g_xn + (size_t)row * DD + c1) = o1;
        }
    }
}

// ---------------- pooling: per-graph sum of (agg2 * ndst) ----------------
__global__ void __launch_bounds__(256) k_pool(const int* __restrict__ gid, int N) {
    __shared__ float acc[GG * DD];
    __shared__ float cnt[GG];
    int t = threadIdx.x;
    for (int i = t; i < GG * DD; i += 256) acc[i] = 0.f;
    if (t < GG) cnt[t] = 0.f;
    __syncthreads();

    int chunk = (N + gridDim.x - 1) / gridDim.x;
    int base = blockIdx.x * chunk;
    int end = min(base + chunk, N);
    int warp = t >> 5, lane = t & 31;
    for (int n = base + warp; n < end; n += 8) {
        int g = gid[n];
        float s = g_ndst[n];
        float4 v = *(const float4*)(g_agg + (size_t)n * DD + lane * 4);
        float* p = &acc[g * DD + lane * 4];
        atomicAdd(p + 0, v.x * s);
        atomicAdd(p + 1, v.y * s);
        atomicAdd(p + 2, v.z * s);
        atomicAdd(p + 3, v.w * s);
        if (lane == 0) atomicAdd(&cnt[g], 1.f);
    }
    __syncthreads();
    for (int i = t; i < GG * DD; i += 256) atomicAdd(&g_pool[i], acc[i]);
    if (t < GG) atomicAdd(&g_cnt[t], cnt[t]);
}

__global__ void k_final(const float* __restrict__ W2, const float* __restrict__ b2,
                        float* __restrict__ out) {
    __shared__ float srow[DD];
    int g = blockIdx.x, t = threadIdx.x;
    srow[t] = g_pool[g * DD + t] / fmaxf(g_cnt[g], 1.f);
    __syncthreads();
    float a = b2[t];
#pragma unroll 8
    for (int k = 0; k < DD; k++) a += srow[k] * W2[k * DD + t];
    out[g * DD + t] = a;
}

// ---------------- launch ----------------
extern "C" void kernel_launch(void* const* d_in, const int* in_sizes, int n_in,
                              void* d_out, int out_size) {
    const float* in_feat = (const float*)d_in[0];
    const float* W1 = (const float*)d_in[1];
    const float* b1 = (const float*)d_in[2];
    const float* W2 = (const float*)d_in[3];
    const float* b2 = (const float*)d_in[4];
    const int* src = (const int*)d_in[5];
    const int* dst = (const int*)d_in[6];
    const int* gid = (const int*)d_in[7];
    int N = in_sizes[0] / DD;
    int E = in_sizes[5];
    (void)n_in; (void)out_size;

    void *p_agg, *p_xn, *p_do, *p_di, *p_pool, *p_cnt;
    cudaGetSymbolAddress(&p_agg, g_agg);
    cudaGetSymbolAddress(&p_xn, g_xn);
    cudaGetSymbolAddress(&p_do, g_deg_out);
    cudaGetSymbolAddress(&p_di, g_deg_in);
    cudaGetSymbolAddress(&p_pool, g_pool);
    cudaGetSymbolAddress(&p_cnt, g_cnt);

    static int smem_set = 0;
    if (!smem_set) {
        cudaFuncSetAttribute(k_gemm1, cudaFuncAttributeMaxDynamicSharedMemorySize,
                             (64 * 128 + 128 * 128) * (int)sizeof(float));
        smem_set = 1;
    }

    cudaMemsetAsync(p_do, 0, N * sizeof(int));
    cudaMemsetAsync(p_di, 0, N * sizeof(int));
    cudaMemsetAsync(p_pool, 0, GG * DD * sizeof(float));
    cudaMemsetAsync(p_cnt, 0, GG * sizeof(float));

    k_degree<<<1024, 256>>>(src, dst, E);
    k_norm<<<(N + 255) / 256, 256>>>(N);

    // CSR-by-dst build (counting sort)
    int B = (N + 1023) / 1024;
    k_scan1<<<B, 256>>>(N);
    k_scan2<<<1, 128>>>(B);
    k_scan3<<<(N + 255) / 256, 256>>>(N, E);
    k_scatter<<<(E + 255) / 256, 256>>>(src, dst, E);

    // layer 1: aggregate (gather, nsrc fused) then dense
    k_spmm_seg<true><<<(N + 7) / 8, 256>>>(in_feat, (float*)p_agg, N);
    k_gemm1<<<(N + 63) / 64, 256, (64 * 128 + 128 * 128) * sizeof(float)>>>(W1, b1, N);

    // layer 2: aggregate
    k_spmm_seg<false><<<(N + 7) / 8, 256>>>((const float*)p_xn, (float*)p_agg, N);

    k_pool<<<200, 256>>>(gid, N);
    k_final<<<GG, DD>>>(W2, b2, (float*)d_out);
}

// round 3
// speedup vs baseline: 1.9514x; 1.0347x over previous
#include <cuda_runtime.h>
#include <cuda_bf16.h>
#include <cstdint>

#define NN 100000
#define EE 1600000
#define DD 128
#define GG 64

// ---------------- device scratch ----------------
__device__ float    g_agg[(size_t)NN * DD];     // spmm1 output (fp32)
__device__ unsigned g_xh[(size_t)NN * DD / 2];  // bf16x2 features (layer1 in / layer2 in)
__device__ int   g_deg_out[NN];
__device__ int   g_deg_in[NN];
__device__ float g_nsrc[NN];
__device__ float g_ndst[NN];
__device__ float g_pool[GG * DD];
__device__ float g_cnt[GG];
__device__ int   g_off[NN + 1];
__device__ int   g_cursor[NN];
__device__ int   g_sorted[EE];
__device__ int   g_bsum[128];

// ---------------- helpers ----------------
__device__ __forceinline__ unsigned f2tf32(float x) {
    unsigned r;
    asm("cvt.rna.tf32.f32 %0, %1;" : "=r"(r) : "f"(x));
    return r;
}
__device__ __forceinline__ unsigned pack_bf16x2(float lo, float hi) {
    unsigned r;  // first src -> upper half, second -> lower half
    asm("cvt.rn.bf16x2.f32 %0, %1, %2;" : "=r"(r) : "f"(hi), "f"(lo));
    return r;
}
__device__ __forceinline__ void mma_tf32(float& d0, float& d1, float& d2, float& d3,
                                         unsigned a0, unsigned a1, unsigned a2, unsigned a3,
                                         unsigned b0, unsigned b1) {
    asm("mma.sync.aligned.m16n8k8.row.col.f32.tf32.tf32.f32 "
        "{%0,%1,%2,%3}, {%4,%5,%6,%7}, {%8,%9}, {%0,%1,%2,%3};"
        : "+f"(d0), "+f"(d1), "+f"(d2), "+f"(d3)
        : "r"(a0), "r"(a1), "r"(a2), "r"(a3), "r"(b0), "r"(b1));
}
__device__ __forceinline__ void acc_bf16(float4& a, uint2 u) {
    a.x += __uint_as_float(u.x << 16);
    a.y += __uint_as_float(u.x & 0xffff0000u);
    a.z += __uint_as_float(u.y << 16);
    a.w += __uint_as_float(u.y & 0xffff0000u);
}

// ---------------- degree / norm / counts ----------------
__global__ void k_degree(const int* __restrict__ src, const int* __restrict__ dst, int E) {
    int i = blockIdx.x * blockDim.x + threadIdx.x;
    int stride = gridDim.x * blockDim.x;
    for (; i < E; i += stride) {
        atomicAdd(&g_deg_out[src[i]], 1);
        atomicAdd(&g_deg_in[dst[i]], 1);
    }
}

__global__ void k_norm(const int* __restrict__ gid, int N) {
    int i = blockIdx.x * blockDim.x + threadIdx.x;
    if (i < N) {
        g_nsrc[i] = rsqrtf((float)max(g_deg_out[i], 1));
        g_ndst[i] = rsqrtf((float)max(g_deg_in[i], 1));
        atomicAdd(&g_cnt[gid[i]], 1.f);
    }
}

// ---------------- scan (CSR offsets from deg_in) ----------------
__global__ void k_scan1(int N) {
    __shared__ int s[256];
    int t = threadIdx.x;
    int base = blockIdx.x * 1024 + t * 4;
    int v0 = 0, v1 = 0, v2 = 0, v3 = 0;
    if (base + 0 < N) v0 = g_deg_in[base + 0];
    if (base + 1 < N) v1 = g_deg_in[base + 1];
    if (base + 2 < N) v2 = g_deg_in[base + 2];
    if (base + 3 < N) v3 = g_deg_in[base + 3];
    int tsum = v0 + v1 + v2 + v3;
    s[t] = tsum;
    __syncthreads();
    for (int o = 1; o < 256; o <<= 1) {
        int x = (t >= o) ? s[t - o] : 0;
        __syncthreads();
        s[t] += x;
        __syncthreads();
    }
    int incl = s[t];
    int excl = incl - tsum;
    if (base + 0 < N) g_off[base + 0] = excl;
    if (base + 1 < N) g_off[base + 1] = excl + v0;
    if (base + 2 < N) g_off[base + 2] = excl + v0 + v1;
    if (base + 3 < N) g_off[base + 3] = excl + v0 + v1 + v2;
    if (t == 255) g_bsum[blockIdx.x] = incl;
}

__global__ void k_scan2(int B) {
    __shared__ int s[128];
    int t = threadIdx.x;
    int v = (t < B) ? g_bsum[t] : 0;
    s[t] = v;
    __syncthreads();
    for (int o = 1; o < 128; o <<= 1) {
        int x = (t >= o) ? s[t - o] : 0;
        __syncthreads();
        s[t] += x;
        __syncthreads();
    }
    if (t < B) g_bsum[t] = s[t] - v;
}

__global__ void k_scan3(int N, int E) {
    int i = blockIdx.x * blockDim.x + threadIdx.x;
    if (i < N) {
        int o = g_off[i] + g_bsum[i >> 10];
        g_off[i] = o;
        g_cursor[i] = o;
    }
    if (i == 0) g_off[N] = E;
}

__global__ void k_scatter(const int* __restrict__ src, const int* __restrict__ dst, int E) {
    int i = blockIdx.x * blockDim.x + threadIdx.x;
    if (i < E) {
        int d = dst[i];
        int p = atomicAdd(&g_cursor[d], 1);
        g_sorted[p] = src[i];
    }
}

// ---------------- prep: g_xh = bf16(in_feat * nsrc) ----------------
__global__ void k_prep(const float* __restrict__ x, int N) {
    int i = blockIdx.x * blockDim.x + threadIdx.x;  // over N*32 float4s
    if (i >= N * 32) return;
    int n = i >> 5;
    float s = g_nsrc[n];
    float4 v = ((const float4*)x)[i];
    uint2 u;
    u.x = pack_bf16x2(v.x * s, v.y * s);
    u.y = pack_bf16x2(v.z * s, v.w * s);
    ((uint2*)g_xh)[i] = u;
}

// ---------------- SpMM layer 1: one warp per dst node, bf16 gather -> fp32 out ----------------
__global__ void __launch_bounds__(256) k_spmm1(int N) {
    int warp = (blockIdx.x * blockDim.x + threadIdx.x) >> 5;
    if (warp >= N) return;
    int lane = threadIdx.x & 31;
    const uint2* xh = (const uint2*)g_xh;
    int e = g_off[warp];
    int e1 = g_off[warp + 1];
    float4 acc = make_float4(0.f, 0.f, 0.f, 0.f);
    for (; e + 4 <= e1; e += 4) {
        int s0 = g_sorted[e + 0];
        int s1 = g_sorted[e + 1];
        int s2 = g_sorted[e + 2];
        int s3 = g_sorted[e + 3];
        uint2 u0 = xh[(size_t)s0 * 32 + lane];
        uint2 u1 = xh[(size_t)s1 * 32 + lane];
        uint2 u2 = xh[(size_t)s2 * 32 + lane];
        uint2 u3 = xh[(size_t)s3 * 32 + lane];
        acc_bf16(acc, u0); acc_bf16(acc, u1); acc_bf16(acc, u2); acc_bf16(acc, u3);
    }
    for (; e < e1; e++) {
        uint2 u = xh[(size_t)g_sorted[e] * 32 + lane];
        acc_bf16(acc, u);
    }
    *(float4*)(g_agg + (size_t)warp * DD + lane * 4) = acc;
}

// ---------------- fused dense stage 1 (tf32 tensor cores) ----------------
// g_xh = bf16( relu((g_agg*ndst) @ W1 + b1) * nsrc )
// BM=64 rows/block, full 128 cols, K=128. 256 thr = 8 warps (2m x 4n), warp tile 32x32.
#define SA_STRIDE 136
#define SW_STRIDE 136
__global__ void __launch_bounds__(256) k_gemm1(const float* __restrict__ W,
                                               const float* __restrict__ b, int N) {
    extern __shared__ float smem[];
    float* sA = smem;                      // 64 x 136
    float* sW = smem + 64 * SA_STRIDE;     // 128 x 136

    int t = threadIdx.x;
    int row0 = blockIdx.x * 64;
    int wid = t >> 5;
    int lane = t & 31;
    int g = lane >> 2;      // groupID
    int tg = lane & 3;      // thread-in-group
    int wm = wid >> 2;      // 0..1
    int wn = wid & 3;       // 0..3

    // stage W: 128x128 -> sW (stride 136)
#pragma unroll
    for (int i = 0; i < 16; i++) {
        int f = t + i * 256;        // 0..4095 float4s
        int r = f >> 5;
        int c = f & 31;
        float4 v = *(const float4*)(W + r * 128 + c * 4);
        *(float4*)(sW + r * SW_STRIDE + c * 4) = v;
    }
    // stage A: 64x128, scaled by ndst
#pragma unroll
    for (int i = 0; i < 8; i++) {
        int f = t + i * 256;        // 0..2047 float4s
        int r = f >> 5;
        int c = f & 31;
        int row = row0 + r;
        float4 v = make_float4(0.f, 0.f, 0.f, 0.f);
        if (row < N) {
            v = *(const float4*)(g_agg + (size_t)row * DD + c * 4);
            float s = g_ndst[row];
            v.x *= s; v.y *= s; v.z *= s; v.w *= s;
        }
        *(float4*)(sA + r * SA_STRIDE + c * 4) = v;
    }
    __syncthreads();

    float acc[2][4][4];
#pragma unroll
    for (int i = 0; i < 2; i++)
#pragma unroll
        for (int j = 0; j < 4; j++)
#pragma unroll
            for (int q = 0; q < 4; q++) acc[i][j][q] = 0.f;

    const float* pA = sA + (wm * 32 + g) * SA_STRIDE + tg;
    const float* pB = sW + tg * SW_STRIDE + wn * 32 + g;

#pragma unroll
    for (int ks = 0; ks < 16; ks++) {
        int k0 = ks * 8;
        unsigned a[2][4];
#pragma unroll
        for (int i = 0; i < 2; i++) {
            const float* p = pA + i * 16 * SA_STRIDE + k0;
            a[i][0] = f2tf32(p[0]);
            a[i][1] = f2tf32(p[8 * SA_STRIDE]);
            a[i][2] = f2tf32(p[4]);
            a[i][3] = f2tf32(p[8 * SA_STRIDE + 4]);
        }
        unsigned bb[4][2];
#pragma unroll
        for (int j = 0; j < 4; j++) {
            const float* p = pB + k0 * SW_STRIDE + j * 8;
            bb[j][0] = f2tf32(p[0]);
            bb[j][1] = f2tf32(p[4 * SW_STRIDE]);
        }
#pragma unroll
        for (int i = 0; i < 2; i++)
#pragma unroll
            for (int j = 0; j < 4; j++)
                mma_tf32(acc[i][j][0], acc[i][j][1], acc[i][j][2], acc[i][j][3],
                         a[i][0], a[i][1], a[i][2], a[i][3], bb[j][0], bb[j][1]);
    }

    // epilogue: +bias, relu, *nsrc, bf16 pack, store
#pragma unroll
    for (int i = 0; i < 2; i++) {
        int rA = row0 + wm * 32 + i * 16 + g;
        int rB = rA + 8;
        float sA_ = (rA < N) ? g_nsrc[rA] : 0.f;
        float sB_ = (rB < N) ? g_nsrc[rB] : 0.f;
#pragma unroll
        for (int j = 0; j < 4; j++) {
            int c = wn * 32 + j * 8 + tg * 2;
            float bx = b[c], by = b[c + 1];
            if (rA < N) {
                float x0 = fmaxf(acc[i][j][0] + bx, 0.f) * sA_;
                float x1 = fmaxf(acc[i][j][1] + by, 0.f) * sA_;
                g_xh[(size_t)rA * 64 + (c >> 1)] = pack_bf16x2(x0, x1);
            }
            if (rB < N) {
                float x2 = fmaxf(acc[i][j][2] + bx, 0.f) * sB_;
                float x3 = fmaxf(acc[i][j][3] + by, 0.f) * sB_;
                g_xh[(size_t)rB * 64 + (c >> 1)] = pack_bf16x2(x2, x3);
            }
        }
    }
}

// ---------------- SpMM layer 2 fused with pooling ----------------
__global__ void __launch_bounds__(256) k_spmm2pool(const int* __restrict__ gid, int N) {
    __shared__ float pool[GG * DD];
    int t = threadIdx.x;
    for (int i = t; i < GG * DD; i += 256) pool[i] = 0.f;
    __syncthreads();

    int lane = t & 31;
    const uint2* xh = (const uint2*)g_xh;
    int w = (blockIdx.x * 256 + t) >> 5;
    int nw = gridDim.x * 8;
    for (int n = w; n < N; n += nw) {
        int e = g_off[n];
        int e1 = g_off[n + 1];
        float4 acc = make_float4(0.f, 0.f, 0.f, 0.f);
        for (; e + 4 <= e1; e += 4) {
            int s0 = g_sorted[e + 0];
            int s1 = g_sorted[e + 1];
            int s2 = g_sorted[e + 2];
            int s3 = g_sorted[e + 3];
            uint2 u0 = xh[(size_t)s0 * 32 + lane];
            uint2 u1 = xh[(size_t)s1 * 32 + lane];
            uint2 u2 = xh[(size_t)s2 * 32 + lane];
            uint2 u3 = xh[(size_t)s3 * 32 + lane];
            acc_bf16(acc, u0); acc_bf16(acc, u1); acc_bf16(acc, u2); acc_bf16(acc, u3);
        }
        for (; e < e1; e++) {
            uint2 u = xh[(size_t)g_sorted[e] * 32 + lane];
            acc_bf16(acc, u);
        }
        float s = g_ndst[n];
        float* p = &pool[gid[n] * DD + lane * 4];
        atomicAdd(p + 0, acc.x * s);
        atomicAdd(p + 1, acc.y * s);
        atomicAdd(p + 2, acc.z * s);
        atomicAdd(p + 3, acc.w * s);
    }
    __syncthreads();
    for (int i = t; i < GG * DD; i += 256) atomicAdd(&g_pool[i], pool[i]);
}

// ---------------- final: out = (pool/cnt) @ W2 + b2 ----------------
__global__ void k_final(const float* __restrict__ W2, const float* __restrict__ b2,
                        float* __restrict__ out) {
    __shared__ float srow[DD];
    int gph = blockIdx.x, t = threadIdx.x;
    srow[t] = g_pool[gph * DD + t] / fmaxf(g_cnt[gph], 1.f);
    __syncthreads();
    float a = b2[t];
#pragma unroll 8
    for (int k = 0; k < DD; k++) a += srow[k] * W2[k * DD + t];
    out[gph * DD + t] = a;
}

// ---------------- launch ----------------
extern "C" void kernel_launch(void* const* d_in, const int* in_sizes, int n_in,
                              void* d_out, int out_size) {
    const float* in_feat = (const float*)d_in[0];
    const float* W1 = (const float*)d_in[1];
    const float* b1 = (const float*)d_in[2];
    const float* W2 = (const float*)d_in[3];
    const float* b2 = (const float*)d_in[4];
    const int* src = (const int*)d_in[5];
    const int* dst = (const int*)d_in[6];
    const int* gid = (const int*)d_in[7];
    int N = in_sizes[0] / DD;
    int E = in_sizes[5];
    (void)n_in; (void)out_size;

    void *p_do, *p_di, *p_pool, *p_cnt;
    cudaGetSymbolAddress(&p_do, g_deg_out);
    cudaGetSymbolAddress(&p_di, g_deg_in);
    cudaGetSymbolAddress(&p_pool, g_pool);
    cudaGetSymbolAddress(&p_cnt, g_cnt);

    const int gemm_smem = (64 * SA_STRIDE + 128 * SW_STRIDE) * (int)sizeof(float);
    static int smem_set = 0;
    if (!smem_set) {
        cudaFuncSetAttribute(k_gemm1, cudaFuncAttributeMaxDynamicSharedMemorySize, gemm_smem);
        smem_set = 1;
    }

    cudaMemsetAsync(p_do, 0, N * sizeof(int));
    cudaMemsetAsync(p_di, 0, N * sizeof(int));
    cudaMemsetAsync(p_pool, 0, GG * DD * sizeof(float));
    cudaMemsetAsync(p_cnt, 0, GG * sizeof(float));

    k_degree<<<1024, 256>>>(src, dst, E);
    k_norm<<<(N + 255) / 256, 256>>>(gid, N);

    int B = (N + 1023) / 1024;
    k_scan1<<<B, 256>>>(N);
    k_scan2<<<1, 128>>>(B);
    k_scan3<<<(N + 255) / 256, 256>>>(N, E);
    k_scatter<<<(E + 255) / 256, 256>>>(src, dst, E);

    k_prep<<<(N * 32 + 255) / 256, 256>>>(in_feat, N);
    k_spmm1<<<(N + 7) / 8, 256>>>(N);
    k_gemm1<<<(N + 63) / 64, 256, gemm_smem>>>(W1, b1, N);
    k_spmm2pool<<<296, 256>>>(gid, N);
    k_final<<<GG, DD>>>(W2, b2, (float*)d_out);
}